// round 4
// baseline (speedup 1.0000x reference)
#include <cuda_runtime.h>
#include <cuda_fp16.h>
#include <cstdint>

// RNN: h_t = tanh([h_{t-1} | x_t] @ [W_hh | W_ih]^T + b), out = h_T @ W_out^T + b_out
// fp16-split 3-pass mma.m16n8k16: W = W_hi + W_lo/2048 (each fp16), state likewise.
// acc = W_hi*s_hi + (W_lo*s_hi + W_hi*s_lo)/2048; dropped lo*lo ~ 2^-22.

#define BATCH    4096
#define TSTEPS   512
#define IN_DIM   28
#define HID      64
#define OUT_DIM  10
#define KCOMB    96           // 64 h + 28 x + 4 pad
#define CHUNKS   6            // KCOMB / 16
#define BTILE    32
#define NTHREADS 256          // 8 warps: 2 m-groups x 4 n-groups
#define S        68           // uint32 words per batch-row (48 kpairs + pad; 68 % 32 == 4 -> conflict-free)
#define PLANE    (BTILE * S)  // 2176 words per plane
// smem (floats/words): [buf0_hi|buf0_lo|buf1_hi|buf1_lo][W stage 6144][bias 64]
#define WOFF     (4 * PLANE)            // 8704
#define BIAS_OFF (WOFF + HID * KCOMB)   // 14848
#define SMEM_WORDS (BIAS_OFF + HID)     // 14912
#define SMEM_BYTES (SMEM_WORDS * 4)     // 59648 B

#define INV2048  4.8828125e-4f

__device__ __forceinline__ float fast_tanh(float v) {
    float e = __expf(2.0f * v);
    return 1.0f - __fdividef(2.0f, e + 1.0f);
}

__device__ __forceinline__ uint32_t pack2(__half lo, __half hi) {
    __half2 h = __halves2half2(lo, hi);
    return *reinterpret_cast<uint32_t*>(&h);
}

__device__ __forceinline__ void mma16(float* d, const uint32_t* a, const uint32_t* b) {
    asm volatile(
        "mma.sync.aligned.m16n8k16.row.col.f32.f16.f16.f32 "
        "{%0,%1,%2,%3}, {%4,%5,%6,%7}, {%8,%9}, {%0,%1,%2,%3};"
        : "+f"(d[0]), "+f"(d[1]), "+f"(d[2]), "+f"(d[3])
        : "r"(a[0]), "r"(a[1]), "r"(a[2]), "r"(a[3]), "r"(b[0]), "r"(b[1]));
}

__global__ void __launch_bounds__(NTHREADS, 1)
rnn_fp16_kernel(const float* __restrict__ x,
                const float* __restrict__ W_ih,
                const float* __restrict__ W_hh,
                const float* __restrict__ b_ih,
                const float* __restrict__ b_hh,
                const float* __restrict__ W_out,
                const float* __restrict__ b_out,
                float* __restrict__ out)
{
    extern __shared__ float sm[];
    uint32_t* usm = (uint32_t*)sm;

    const int tid  = threadIdx.x;
    const int b0   = blockIdx.x * BTILE;
    const int lane = tid & 31;
    const int w    = tid >> 5;
    const int mg   = w & 1;        // m-group: W rows [mg*32, mg*32+32)
    const int ng   = w >> 1;       // n-group: batch rows [ng*8, ng*8+8)
    const int gid  = lane >> 2;
    const int tig  = lane & 3;
    const int m0b  = mg * 32;
    const int nb   = ng * 8;

    // ---- Stage combined weight Wc[64][96] fp32 + bias ----
    for (int idx = tid; idx < HID * KCOMB; idx += NTHREADS) {
        int j = idx / KCOMB, k = idx % KCOMB;
        float v = 0.0f;
        if (k < HID)               v = W_hh[j * HID + k];
        else if (k < HID + IN_DIM) v = W_ih[j * IN_DIM + (k - HID)];
        sm[WOFF + idx] = v;
    }
    if (tid < HID) sm[BIAS_OFF + tid] = b_ih[tid] + b_hh[tid];
    __syncthreads();

    // ---- W fragments (A operand, m16k16), hi + scaled-lo fp16 ----
    uint32_t whi[2][CHUNKS][4], wlo[2][CHUNKS][4];
    float biasj[2][2];
#pragma unroll
    for (int mt = 0; mt < 2; mt++) {
        int m0 = m0b + mt * 16;
#pragma unroll
        for (int c = 0; c < CHUNKS; c++) {
#pragma unroll
            for (int r = 0; r < 4; r++) {
                int row = m0 + gid + (r & 1) * 8;
                int k0  = c * 16 + 2 * tig + (r >> 1) * 8;
                float va = sm[WOFF + row * KCOMB + k0];
                float vb = sm[WOFF + row * KCOMB + k0 + 1];
                __half ha = __float2half_rn(va), hb = __float2half_rn(vb);
                whi[mt][c][r] = pack2(ha, hb);
                wlo[mt][c][r] = pack2(
                    __float2half_rn((va - __half2float(ha)) * 2048.0f),
                    __float2half_rn((vb - __half2float(hb)) * 2048.0f));
            }
        }
        biasj[mt][0] = sm[BIAS_OFF + m0 + gid];
        biasj[mt][1] = sm[BIAS_OFF + m0 + gid + 8];
    }
    __syncthreads();

    // ---- Zero both state double-buffers (h=0, pads stay 0) ----
    for (int idx = tid; idx < 4 * PLANE; idx += NTHREADS) sm[idx] = 0.0f;

    // ---- x loader: 224 threads, one float4 (4 k-values) per thread per step ----
    const bool isld = tid < 224;
    const int  xn = isld ? tid / 7 : 0;
    const int  xq = isld ? tid % 7 : 0;
    const float4* xp4 = (const float4*)(x + (size_t)(b0 + xn) * TSTEPS * IN_DIM) + xq;

    float4 xr = make_float4(0, 0, 0, 0);
    if (isld) xr = xp4[0];                    // t = 0
    __syncthreads();                          // zero-fill visible

    auto store_x = [&](int p) {
        int hb = (p * 2) * PLANE + xn * S + 32 + 2 * xq;
        __half h0 = __float2half_rn(xr.x), h1 = __float2half_rn(xr.y);
        __half h2 = __float2half_rn(xr.z), h3 = __float2half_rn(xr.w);
        usm[hb]     = pack2(h0, h1);
        usm[hb + 1] = pack2(h2, h3);
        usm[hb + PLANE]     = pack2(__float2half_rn((xr.x - __half2float(h0)) * 2048.0f),
                                    __float2half_rn((xr.y - __half2float(h1)) * 2048.0f));
        usm[hb + PLANE + 1] = pack2(__float2half_rn((xr.z - __half2float(h2)) * 2048.0f),
                                    __float2half_rn((xr.w - __half2float(h3)) * 2048.0f));
    };
    if (isld) store_x(0);
    __syncthreads();

    const bool evengid = !(gid & 1);
    const int  n0 = nb + 2 * tig;

    int p = 0;
    for (int t = 0; t < TSTEPS; t++) {
        if (isld && t + 1 < TSTEPS) xr = xp4[(t + 1) * 7];   // prefetch

        float accA[2][4], accB[2][4];
#pragma unroll
        for (int mt = 0; mt < 2; mt++) {
            accA[mt][0] = biasj[mt][0]; accA[mt][1] = biasj[mt][0];
            accA[mt][2] = biasj[mt][1]; accA[mt][3] = biasj[mt][1];
            accB[mt][0] = accB[mt][1] = accB[mt][2] = accB[mt][3] = 0.0f;
        }

        const int hbase = (p * 2) * PLANE + (nb + gid) * S;
        const int lbase = hbase + PLANE;
#pragma unroll
        for (int c = 0; c < CHUNKS; c++) {
            uint32_t bh[2], bl[2];
            bh[0] = usm[hbase + c * 8 + tig];
            bh[1] = usm[hbase + c * 8 + tig + 4];
            bl[0] = usm[lbase + c * 8 + tig];
            bl[1] = usm[lbase + c * 8 + tig + 4];
            mma16(accA[0], whi[0][c], bh);
            mma16(accA[1], whi[1][c], bh);
            mma16(accB[0], wlo[0][c], bh);
            mma16(accB[1], wlo[1][c], bh);
            mma16(accB[0], whi[0][c], bl);
            mma16(accB[1], whi[1][c], bl);
        }

        // tanh -> shfl-pair -> fp16-split -> store into buffer q
        const int q = p ^ 1;
#pragma unroll
        for (int mt = 0; mt < 2; mt++) {
            float v0 = fast_tanh(accA[mt][0] + accB[mt][0] * INV2048);
            float v1 = fast_tanh(accA[mt][1] + accB[mt][1] * INV2048);
            float v2 = fast_tanh(accA[mt][2] + accB[mt][2] * INV2048);
            float v3 = fast_tanh(accA[mt][3] + accB[mt][3] * INV2048);

            // exchange across j-pair partner (lane ^ 4)
            float s0 = evengid ? v2 : v0;
            float s1 = evengid ? v3 : v1;
            float r0 = __shfl_xor_sync(0xffffffffu, s0, 4);
            float r1 = __shfl_xor_sync(0xffffffffu, s1, 4);

            int m0 = m0b + mt * 16;
            int kp = evengid ? ((m0 + gid) >> 1) : ((m0 + gid + 7) >> 1);
            float a0 = evengid ? v0 : r0;   // lower-j value, col n0
            float c0 = evengid ? r0 : v2;   // upper-j value, col n0
            float a1 = evengid ? v1 : r1;   // col n0+1
            float c1 = evengid ? r1 : v3;

            __half ha0 = __float2half_rn(a0), hc0 = __float2half_rn(c0);
            __half ha1 = __float2half_rn(a1), hc1 = __float2half_rn(c1);
            int whb = (q * 2) * PLANE + n0 * S + kp;
            usm[whb]     = pack2(ha0, hc0);
            usm[whb + S] = pack2(ha1, hc1);
            usm[whb + PLANE]     = pack2(__float2half_rn((a0 - __half2float(ha0)) * 2048.0f),
                                         __float2half_rn((c0 - __half2float(hc0)) * 2048.0f));
            usm[whb + PLANE + S] = pack2(__float2half_rn((a1 - __half2float(ha1)) * 2048.0f),
                                         __float2half_rn((c1 - __half2float(hc1)) * 2048.0f));
        }

        if (isld && t + 1 < TSTEPS) store_x(q);
        __syncthreads();
        p = q;
    }

    // ---- Output projection ----
    for (int idx = tid; idx < OUT_DIM * HID; idx += NTHREADS) sm[WOFF + idx] = W_out[idx];
    if (tid < OUT_DIM) sm[BIAS_OFF + tid] = b_out[tid];
    __syncthreads();

    const int hb = (p * 2) * PLANE;
    for (int idx = tid; idx < BTILE * OUT_DIM; idx += NTHREADS) {
        int n = idx / OUT_DIM, o = idx % OUT_DIM;
        float s = sm[BIAS_OFF + o];
#pragma unroll 8
        for (int jp = 0; jp < HID / 2; jp++) {
            __half2 hh = *reinterpret_cast<const __half2*>(&usm[hb + n * S + jp]);
            __half2 ll = *reinterpret_cast<const __half2*>(&usm[hb + PLANE + n * S + jp]);
            float2 fh = __half22float2(hh), fl = __half22float2(ll);
            s += (fh.x + fl.x * INV2048) * sm[WOFF + o * HID + 2 * jp]
               + (fh.y + fl.y * INV2048) * sm[WOFF + o * HID + 2 * jp + 1];
        }
        out[(size_t)(b0 + n) * OUT_DIM + o] = s;
    }
}

extern "C" void kernel_launch(void* const* d_in, const int* in_sizes, int n_in,
                              void* d_out, int out_size)
{
    const float* x     = (const float*)d_in[0];
    const float* W_ih  = (const float*)d_in[1];
    const float* W_hh  = (const float*)d_in[2];
    const float* b_ih  = (const float*)d_in[3];
    const float* b_hh  = (const float*)d_in[4];
    const float* W_out = (const float*)d_in[5];
    const float* b_out = (const float*)d_in[6];
    float* out = (float*)d_out;

    cudaFuncSetAttribute(rnn_fp16_kernel,
                         cudaFuncAttributeMaxDynamicSharedMemorySize, SMEM_BYTES);

    dim3 grid(BATCH / BTILE);   // 128 CTAs, 32 persistent batch rows each
    dim3 block(NTHREADS);       // 8 warps
    rnn_fp16_kernel<<<grid, block, SMEM_BYTES>>>(x, W_ih, W_hh, b_ih, b_hh,
                                                 W_out, b_out, out);
}

// round 6
// speedup vs baseline: 1.2933x; 1.2933x over previous
#include <cuda_runtime.h>
#include <cuda_fp16.h>
#include <cstdint>

// RNN: h_t = tanh([h_{t-1} | x_t] @ [W_hh | W_ih]^T + b), out = h_T @ W_out^T + b_out
// fp16-split 3-pass mma.m16n8k16: W = W_hi + W_lo/2048, state likewise.
// acc = W_hi*s_hi + (W_lo*s_hi + W_hi*s_lo)/2048; dropped lo*lo ~ 2^-22.
// Round 4: BTILE=8, 64-thread CTAs, 512 CTAs -> 3-4 independent chains per SM.

#define BATCH    4096
#define TSTEPS   512
#define IN_DIM   28
#define HID      64
#define OUT_DIM  10
#define KCOMB    96           // 64 h + 28 x + 4 pad
#define CHUNKS   6            // KCOMB / 16
#define BTILE    8
#define NTHREADS 64           // 2 warps, each m=32 (mg), n=8 (all rows)
#define S        68           // words per batch-row; 68 % 32 == 4 -> conflict-free maps
#define PLANE    (BTILE * S)  // 544 words per plane
// smem words: [buf0_hi|buf0_lo|buf1_hi|buf1_lo][W stage 6144][bias 64]
#define WOFF     (4 * PLANE)            // 2176
#define BIAS_OFF (WOFF + HID * KCOMB)   // 8320
#define SMEM_WORDS (BIAS_OFF + HID)     // 8384
#define SMEM_BYTES (SMEM_WORDS * 4)     // 33536 B

#define INV2048  4.8828125e-4f

__device__ __forceinline__ float fast_tanh(float v) {
    float e = __expf(2.0f * v);
    return 1.0f - __fdividef(2.0f, e + 1.0f);
}

__device__ __forceinline__ uint32_t pack2(__half lo, __half hi) {
    __half2 h = __halves2half2(lo, hi);
    return *reinterpret_cast<uint32_t*>(&h);
}

__device__ __forceinline__ void mma16(float* d, const uint32_t* a, const uint32_t* b) {
    asm volatile(
        "mma.sync.aligned.m16n8k16.row.col.f32.f16.f16.f32 "
        "{%0,%1,%2,%3}, {%4,%5,%6,%7}, {%8,%9}, {%0,%1,%2,%3};"
        : "+f"(d[0]), "+f"(d[1]), "+f"(d[2]), "+f"(d[3])
        : "r"(a[0]), "r"(a[1]), "r"(a[2]), "r"(a[3]), "r"(b[0]), "r"(b[1]));
}

__global__ void __launch_bounds__(NTHREADS, 4)
rnn_fp16_kernel(const float* __restrict__ x,
                const float* __restrict__ W_ih,
                const float* __restrict__ W_hh,
                const float* __restrict__ b_ih,
                const float* __restrict__ b_hh,
                const float* __restrict__ W_out,
                const float* __restrict__ b_out,
                float* __restrict__ out)
{
    extern __shared__ float sm[];
    uint32_t* usm = (uint32_t*)sm;

    const int tid  = threadIdx.x;
    const int b0   = blockIdx.x * BTILE;
    const int lane = tid & 31;
    const int mg   = tid >> 5;     // warp id = m-group: W rows [mg*32, mg*32+32)
    const int gid  = lane >> 2;
    const int tig  = lane & 3;
    const int m0b  = mg * 32;

    // ---- Stage combined weight Wc[64][96] fp32 + bias ----
    for (int idx = tid; idx < HID * KCOMB; idx += NTHREADS) {
        int j = idx / KCOMB, k = idx % KCOMB;
        float v = 0.0f;
        if (k < HID)               v = W_hh[j * HID + k];
        else if (k < HID + IN_DIM) v = W_ih[j * IN_DIM + (k - HID)];
        sm[WOFF + idx] = v;
    }
    if (tid < HID) sm[BIAS_OFF + tid] = b_ih[tid] + b_hh[tid];
    __syncthreads();

    // ---- W fragments (A operand, m16k16), hi + scaled-lo fp16 ----
    uint32_t whi[2][CHUNKS][4], wlo[2][CHUNKS][4];
    float biasj[2][2];
#pragma unroll
    for (int mt = 0; mt < 2; mt++) {
        int m0 = m0b + mt * 16;
#pragma unroll
        for (int c = 0; c < CHUNKS; c++) {
#pragma unroll
            for (int r = 0; r < 4; r++) {
                int row = m0 + gid + (r & 1) * 8;
                int k0  = c * 16 + 2 * tig + (r >> 1) * 8;
                float va = sm[WOFF + row * KCOMB + k0];
                float vb = sm[WOFF + row * KCOMB + k0 + 1];
                __half ha = __float2half_rn(va), hb = __float2half_rn(vb);
                whi[mt][c][r] = pack2(ha, hb);
                wlo[mt][c][r] = pack2(
                    __float2half_rn((va - __half2float(ha)) * 2048.0f),
                    __float2half_rn((vb - __half2float(hb)) * 2048.0f));
            }
        }
        biasj[mt][0] = sm[BIAS_OFF + m0 + gid];
        biasj[mt][1] = sm[BIAS_OFF + m0 + gid + 8];
    }
    __syncthreads();

    // ---- Zero both state double-buffers (h=0, pads stay 0) ----
    for (int idx = tid; idx < 4 * PLANE; idx += NTHREADS) sm[idx] = 0.0f;

    // ---- x loader: 56 threads, one float4 (4 k-values) per thread per step ----
    const bool isld = tid < 56;
    const int  xn = isld ? tid / 7 : 0;
    const int  xq = isld ? tid % 7 : 0;
    const float4* xp4 = (const float4*)(x + (size_t)(b0 + xn) * TSTEPS * IN_DIM) + xq;

    float4 xr = make_float4(0, 0, 0, 0);
    if (isld) xr = xp4[0];                    // t = 0
    __syncthreads();                          // zero-fill visible

    auto store_x = [&](int p) {
        int hb = (p * 2) * PLANE + xn * S + 32 + 2 * xq;
        __half h0 = __float2half_rn(xr.x), h1 = __float2half_rn(xr.y);
        __half h2 = __float2half_rn(xr.z), h3 = __float2half_rn(xr.w);
        usm[hb]     = pack2(h0, h1);
        usm[hb + 1] = pack2(h2, h3);
        usm[hb + PLANE]     = pack2(__float2half_rn((xr.x - __half2float(h0)) * 2048.0f),
                                    __float2half_rn((xr.y - __half2float(h1)) * 2048.0f));
        usm[hb + PLANE + 1] = pack2(__float2half_rn((xr.z - __half2float(h2)) * 2048.0f),
                                    __float2half_rn((xr.w - __half2float(h3)) * 2048.0f));
    };
    if (isld) store_x(0);
    __syncthreads();

    const bool evengid = !(gid & 1);
    const int  n0 = 2 * tig;                  // batch rows n0, n0+1 (0..7)

    int p = 0;
    for (int t = 0; t < TSTEPS; t++) {
        if (isld && t + 1 < TSTEPS) xr = xp4[(t + 1) * 7];   // prefetch

        // 4 independent accumulation chains per warp, depth 6 each
        float accA[2][4], accB1[2][4], accB2[2][4];
#pragma unroll
        for (int mt = 0; mt < 2; mt++) {
            accA[mt][0] = biasj[mt][0]; accA[mt][1] = biasj[mt][0];
            accA[mt][2] = biasj[mt][1]; accA[mt][3] = biasj[mt][1];
#pragma unroll
            for (int r = 0; r < 4; r++) { accB1[mt][r] = 0.0f; accB2[mt][r] = 0.0f; }
        }

        const int hbase = (p * 2) * PLANE + gid * S;   // row = gid (0..7)
        const int lbase = hbase + PLANE;
#pragma unroll
        for (int c = 0; c < CHUNKS; c++) {
            uint32_t bh[2], bl[2];
            bh[0] = usm[hbase + c * 8 + tig];
            bh[1] = usm[hbase + c * 8 + tig + 4];
            bl[0] = usm[lbase + c * 8 + tig];
            bl[1] = usm[lbase + c * 8 + tig + 4];
            mma16(accA[0],  whi[0][c], bh);
            mma16(accA[1],  whi[1][c], bh);
            mma16(accB1[0], wlo[0][c], bh);
            mma16(accB1[1], wlo[1][c], bh);
            mma16(accB2[0], whi[0][c], bl);
            mma16(accB2[1], whi[1][c], bl);
        }

        // tanh -> shfl-pair -> fp16-split -> store into buffer q
        const int q = p ^ 1;
#pragma unroll
        for (int mt = 0; mt < 2; mt++) {
            float v0 = fast_tanh(accA[mt][0] + (accB1[mt][0] + accB2[mt][0]) * INV2048);
            float v1 = fast_tanh(accA[mt][1] + (accB1[mt][1] + accB2[mt][1]) * INV2048);
            float v2 = fast_tanh(accA[mt][2] + (accB1[mt][2] + accB2[mt][2]) * INV2048);
            float v3 = fast_tanh(accA[mt][3] + (accB1[mt][3] + accB2[mt][3]) * INV2048);

            // exchange across j-pair partner (lane ^ 4)
            float s0 = evengid ? v2 : v0;
            float s1 = evengid ? v3 : v1;
            float r0 = __shfl_xor_sync(0xffffffffu, s0, 4);
            float r1 = __shfl_xor_sync(0xffffffffu, s1, 4);

            int m0 = m0b + mt * 16;
            int kp = evengid ? ((m0 + gid) >> 1) : ((m0 + gid + 7) >> 1);
            float a0 = evengid ? v0 : r0;   // lower-j value, row n0
            float c0 = evengid ? r0 : v2;   // upper-j value, row n0
            float a1 = evengid ? v1 : r1;   // row n0+1
            float c1 = evengid ? r1 : v3;

            __half ha0 = __float2half_rn(a0), hc0 = __float2half_rn(c0);
            __half ha1 = __float2half_rn(a1), hc1 = __float2half_rn(c1);
            int whb = (q * 2) * PLANE + n0 * S + kp;
            usm[whb]     = pack2(ha0, hc0);
            usm[whb + S] = pack2(ha1, hc1);
            usm[whb + PLANE]     = pack2(__float2half_rn((a0 - __half2float(ha0)) * 2048.0f),
                                         __float2half_rn((c0 - __half2float(hc0)) * 2048.0f));
            usm[whb + PLANE + S] = pack2(__float2half_rn((a1 - __half2float(ha1)) * 2048.0f),
                                         __float2half_rn((c1 - __half2float(hc1)) * 2048.0f));
        }

        if (isld && t + 1 < TSTEPS) store_x(q);
        __syncthreads();
        p = q;
    }

    // ---- Output projection ----
    for (int idx = tid; idx < OUT_DIM * HID; idx += NTHREADS) sm[WOFF + idx] = W_out[idx];
    if (tid < OUT_DIM) sm[BIAS_OFF + tid] = b_out[tid];
    __syncthreads();

    const int hb = (p * 2) * PLANE;
    for (int idx = tid; idx < BTILE * OUT_DIM; idx += NTHREADS) {
        int n = idx / OUT_DIM, o = idx % OUT_DIM;
        float s = sm[BIAS_OFF + o];
#pragma unroll 8
        for (int jp = 0; jp < HID / 2; jp++) {
            __half2 hh = *reinterpret_cast<const __half2*>(&usm[hb + n * S + jp]);
            __half2 ll = *reinterpret_cast<const __half2*>(&usm[hb + PLANE + n * S + jp]);
            float2 fh = __half22float2(hh), fl = __half22float2(ll);
            s += (fh.x + fl.x * INV2048) * sm[WOFF + o * HID + 2 * jp]
               + (fh.y + fl.y * INV2048) * sm[WOFF + o * HID + 2 * jp + 1];
        }
        out[(size_t)(b0 + n) * OUT_DIM + o] = s;
    }
}

extern "C" void kernel_launch(void* const* d_in, const int* in_sizes, int n_in,
                              void* d_out, int out_size)
{
    const float* x     = (const float*)d_in[0];
    const float* W_ih  = (const float*)d_in[1];
    const float* W_hh  = (const float*)d_in[2];
    const float* b_ih  = (const float*)d_in[3];
    const float* b_hh  = (const float*)d_in[4];
    const float* W_out = (const float*)d_in[5];
    const float* b_out = (const float*)d_in[6];
    float* out = (float*)d_out;

    cudaFuncSetAttribute(rnn_fp16_kernel,
                         cudaFuncAttributeMaxDynamicSharedMemorySize, SMEM_BYTES);

    dim3 grid(BATCH / BTILE);   // 512 CTAs, 8 persistent batch rows each
    dim3 block(NTHREADS);       // 2 warps
    rnn_fp16_kernel<<<grid, block, SMEM_BYTES>>>(x, W_ih, W_hh, b_ih, b_hh,
                                                 W_out, b_out, out);
}